// round 14
// baseline (speedup 1.0000x reference)
#include <cuda_runtime.h>

// LSTM_60808146977081: B=4096, T=512, I=10, H=32, fp32.
// R11: gate-split — TWO warps per batch (warp A: gates i,f; warp B: gates g,o).
// Halves weight-register demand (172 -> ~86) so 3 blocks/SM fit (12 warps/SM,
// 3 warps/SMSP, each from a DIFFERENT block) -> one block's activation/sync
// tail overlaps another block's matvec on the same scheduler.
// tanh.approx.f32 activations (sigmoid via 0.5-folded weights), xg overlap,
// 2-step x pipeline as in R7.

#define FULL_MASK 0xFFFFFFFFu

__device__ __forceinline__ float2 ffma2(float2 a, float2 b, float2 c) {
    union F2U { float2 f; unsigned long long u; };
    F2U ua, ub, uc, ud;
    ua.f = a; ub.f = b; uc.f = c;
    asm("fma.rn.f32x2 %0, %1, %2, %3;"
        : "=l"(ud.u) : "l"(ua.u), "l"(ub.u), "l"(uc.u));
    return ud.f;
}

__device__ __forceinline__ float tanh_hw(float x) {
    float r;
    asm("tanh.approx.f32 %0, %1;" : "=f"(r) : "f"(x));
    return r;
}

__global__ void __launch_bounds__(128, 3)
lstm_r11(const float* __restrict__ x,
         const float* __restrict__ h0,
         const float* __restrict__ c0,
         const float* __restrict__ W_ih,
         const float* __restrict__ W_hh,
         const float* __restrict__ b_ih,
         const float* __restrict__ b_hh,
         const float* __restrict__ W_lin,
         const float* __restrict__ b_lin,
         float* __restrict__ out)
{
    constexpr int T = 512;
    constexpr int I = 10;

    const int warp = threadIdx.x >> 5;
    const int lane = threadIdx.x & 31;
    const int pair = warp >> 1;          // 0,1: which batch in this block
    const int half = warp & 1;           // 0: gates i,f   1: gates g,o
    const int b    = blockIdx.x * 2 + pair;

    __shared__ float sh_h [2][32];       // h broadcast per batch
    __shared__ float sh_if[2][2][32];    // ig, fg handoff (A -> B)

    // ---- This warp's 2 gate rows -> registers, activation scale folded ----
    // half0: i (x0.5), f (x0.5).  half1: g (x1.0), o (x0.5).
    float2 wh[2][16];
    float2 wi[2][5];
    float  bias[2];
#pragma unroll
    for (int g = 0; g < 2; g++) {
        const int  gg = half * 2 + g;           // global gate index
        const float s = (gg == 2) ? 1.0f : 0.5f;
        const int  r  = gg * 32 + lane;
        const float2* whp = reinterpret_cast<const float2*>(W_hh + r * 32);
#pragma unroll
        for (int p = 0; p < 16; p++) {
            float2 w = whp[p];
            wh[g][p] = make_float2(w.x * s, w.y * s);
        }
        const float2* wip = reinterpret_cast<const float2*>(W_ih + r * I);
#pragma unroll
        for (int q = 0; q < 5; q++) {
            float2 w = wip[q];
            wi[g][q] = make_float2(w.x * s, w.y * s);
        }
        bias[g] = (b_ih[r] + b_hh[r]) * s;
    }
    const float wl = W_lin[lane];

    // Warp B (half==1) owns c,h state.
    float h = 0.0f, c = 0.0f;
    if (half == 1) {
        h = h0[b * 32 + lane];
        c = c0[b * 32 + lane];
        sh_h[pair][lane] = h;
    }

    // x pipeline (both warps of a batch load the same x -> L1 broadcast hits)
    const float2* xw = reinterpret_cast<const float2*>(x + (size_t)b * (T * I));
    float2 xc[5], xn[5];
    float2 xg[2];
    {
        float2 x0[5];
#pragma unroll
        for (int q = 0; q < 5; q++) x0[q] = xw[q];        // x(0)
#pragma unroll
        for (int q = 0; q < 5; q++) xc[q] = xw[5 + q];    // x(1)
#pragma unroll
        for (int q = 0; q < 5; q++) xn[q] = xw[10 + q];   // x(2)
#pragma unroll
        for (int g = 0; g < 2; g++) {
            xg[g] = make_float2(bias[g], 0.0f);
#pragma unroll
            for (int q = 0; q < 5; q++) xg[g] = ffma2(wi[g][q], x0[q], xg[g]);
        }
    }
    __syncthreads();   // h0 visible

    for (int t = 0; t < T; t++) {
        // ---- Recurrent matvec for this warp's 2 gates ----
        float2 acc[2];
        acc[0] = xg[0];
        acc[1] = xg[1];
        const float4* hp4 = reinterpret_cast<const float4*>(sh_h[pair]);
#pragma unroll
        for (int p = 0; p < 8; p++) {
            const float4 hv = hp4[p];
            const float2 ha = make_float2(hv.x, hv.y);
            const float2 hb = make_float2(hv.z, hv.w);
            acc[0] = ffma2(wh[0][2 * p],     ha, acc[0]);
            acc[0] = ffma2(wh[0][2 * p + 1], hb, acc[0]);
            acc[1] = ffma2(wh[1][2 * p],     ha, acc[1]);
            acc[1] = ffma2(wh[1][2 * p + 1], hb, acc[1]);
        }

        const float y0 = acc[0].x + acc[0].y;
        const float y1 = acc[1].x + acc[1].y;
        const float t0 = tanh_hw(y0);   // half0: pre-ig   half1: gc
        const float t1 = tanh_hw(y1);   // half0: pre-fg   half1: pre-og

        // Overlap MUFU latency with independent work: xg for t+1 + x pipeline
#pragma unroll
        for (int g = 0; g < 2; g++) {
            xg[g] = make_float2(bias[g], 0.0f);
#pragma unroll
            for (int q = 0; q < 5; q++) xg[g] = ffma2(wi[g][q], xc[q], xg[g]);
        }
#pragma unroll
        for (int q = 0; q < 5; q++) xc[q] = xn[q];
        {
            const int tn = (t + 3 < T) ? t + 3 : T - 1;
            const float2* nxt = xw + (size_t)tn * 5;
#pragma unroll
            for (int q = 0; q < 5; q++) xn[q] = nxt[q];
        }

        if (half == 0) {   // gate warp publishes ig, fg
            sh_if[pair][0][lane] = fmaf(0.5f, t0, 0.5f);
            sh_if[pair][1][lane] = fmaf(0.5f, t1, 0.5f);
        }
        __syncthreads();   // S1: ig,fg visible; all h reads done

        if (half == 1) {   // updater warp advances state, publishes h
            const float ig = sh_if[pair][0][lane];
            const float fg = sh_if[pair][1][lane];
            const float og = fmaf(0.5f, t1, 0.5f);
            c = fmaf(fg, c, ig * t0);
            h = og * tanh_hw(c);
            sh_h[pair][lane] = h;
        }
        __syncthreads();   // S2: new h visible
    }

    // out[b] = sum_k h[k] * W_lin[0,k] + b_lin   (updater warp only)
    if (half == 1) {
        float v = h * wl;
#pragma unroll
        for (int off = 16; off; off >>= 1)
            v += __shfl_xor_sync(FULL_MASK, v, off);
        if (lane == 0) out[b] = v + b_lin[0];
    }
}

extern "C" void kernel_launch(void* const* d_in, const int* in_sizes, int n_in,
                              void* d_out, int out_size)
{
    const float* x     = (const float*)d_in[0];
    const float* h0    = (const float*)d_in[1];
    const float* c0    = (const float*)d_in[2];
    const float* W_ih  = (const float*)d_in[3];
    const float* W_hh  = (const float*)d_in[4];
    const float* b_ih  = (const float*)d_in[5];
    const float* b_hh  = (const float*)d_in[6];
    const float* W_lin = (const float*)d_in[7];
    const float* b_lin = (const float*)d_in[8];
    float* out = (float*)d_out;

    // 4096 batches, 2 warps per batch, 2 batches per 128-thread block
    lstm_r11<<<2048, 128>>>(x, h0, c0, W_ih, W_hh, b_ih, b_hh,
                            W_lin, b_lin, out);
}

// round 15
// speedup vs baseline: 1.3851x; 1.3851x over previous
#include <cuda_runtime.h>

// LSTM_60808146977081: B=4096, T=512, I=10, H=32, fp32.
// R14 = R7 + anti-phase stagger. R7: one warp per batch, weights in regs,
// tanh.approx activations (sigmoid 0.5-folded), xg-overlap, 2-step x pipeline.
// NEW: the two co-resident CTAs per SM (hw warp slots 0-3 vs 4-7) are phase-
// locked ("convoy"): both warps on an SMSP hit the MUFU/sync tail together,
// leaving the FMA pipe idle ~50% of each step. A one-time ~200-cycle
// dependent-FFMA delay for the second CTA anti-phases them so one warp's
// matvec fills the other's tail; offset is conserved (identical periods).

#define FULL_MASK 0xFFFFFFFFu

__device__ __forceinline__ float2 ffma2(float2 a, float2 b, float2 c) {
    union F2U { float2 f; unsigned long long u; };
    F2U ua, ub, uc, ud;
    ua.f = a; ub.f = b; uc.f = c;
    asm("fma.rn.f32x2 %0, %1, %2, %3;"
        : "=l"(ud.u) : "l"(ua.u), "l"(ub.u), "l"(uc.u));
    return ud.f;
}

__device__ __forceinline__ float tanh_hw(float x) {
    float r;
    asm("tanh.approx.f32 %0, %1;" : "=f"(r) : "f"(x));
    return r;
}

__global__ void __launch_bounds__(128, 2)
lstm_r14(const float* __restrict__ x,
         const float* __restrict__ h0,
         const float* __restrict__ c0,
         const float* __restrict__ W_ih,
         const float* __restrict__ W_hh,
         const float* __restrict__ b_ih,
         const float* __restrict__ b_hh,
         const float* __restrict__ W_lin,
         const float* __restrict__ b_lin,
         float* __restrict__ out)
{
    constexpr int T = 512;
    constexpr int I = 10;
    // gate fold: sigmoid(y) = 0.5*tanh(0.5*y)+0.5 -> scale i,f,o rows by 0.5.
    const float gscale[4] = { 0.5f, 0.5f, 1.0f, 0.5f };

    const int warp = threadIdx.x >> 5;
    const int lane = threadIdx.x & 31;
    const int b    = blockIdx.x * 4 + warp;

    __shared__ float sh[4][2][32];   // per-warp h broadcast, double-buffered

    // ---- Weights -> registers, pre-scaled by gate fold factor ----
    float2 wh[4][16];   // W_hh rows (gate g*32+lane), pairs along j
    float2 wi[4][5];    // W_ih rows, pairs along i
    float  bias[4];
#pragma unroll
    for (int g = 0; g < 4; g++) {
        const float s = gscale[g];
        const int r = g * 32 + lane;
        const float2* whp = reinterpret_cast<const float2*>(W_hh + r * 32);
#pragma unroll
        for (int p = 0; p < 16; p++) {
            float2 w = whp[p];
            wh[g][p] = make_float2(w.x * s, w.y * s);
        }
        const float2* wip = reinterpret_cast<const float2*>(W_ih + r * I);
#pragma unroll
        for (int q = 0; q < 5; q++) {
            float2 w = wip[q];
            wi[g][q] = make_float2(w.x * s, w.y * s);
        }
        bias[g] = (b_ih[r] + b_hh[r]) * s;
    }
    const float wl = W_lin[lane];

    float h = h0[b * 32 + lane];
    float c = c0[b * 32 + lane];

    const float2* xw = reinterpret_cast<const float2*>(x + (size_t)b * (T * I));

    // x pipeline: xg = x-gate contribution (incl bias) for step t;
    //             xc = x(t+1) (arrived);  xn = x(t+2) (in flight).
    float2 xc[5], xn[5];
    float2 xg[4];
    {
        float2 x0[5];
#pragma unroll
        for (int q = 0; q < 5; q++) x0[q] = xw[q];            // x(0)
#pragma unroll
        for (int q = 0; q < 5; q++) xc[q] = xw[5 + q];        // x(1)
#pragma unroll
        for (int q = 0; q < 5; q++) xn[q] = xw[10 + q];       // x(2)
#pragma unroll
        for (int g = 0; g < 4; g++) {
            xg[g] = make_float2(bias[g], 0.0f);
#pragma unroll
            for (int q = 0; q < 5; q++) xg[g] = ffma2(wi[g][q], x0[q], xg[g]);
        }
    }

    // ---- Anti-phase stagger: second CTA on this SM (hw warp slots >= 4)
    // burns ~200 cycles in a dependent no-op FFMA chain. fma(d,1,0) == d.
    {
        unsigned wslot;
        asm("mov.u32 %0, %%warpid;" : "=r"(wslot));
        if (wslot & 4) {
            float d = h;
#pragma unroll
            for (int i = 0; i < 48; i++)
                asm volatile("fma.rn.f32 %0, %0, 0f3F800000, 0f00000000;"
                             : "+f"(d));
            // d == h numerically (sign-of-zero irrelevant downstream)
            h = d;
        }
    }

#pragma unroll 2
    for (int t = 0; t < T; t++) {
        const int buf = t & 1;
        sh[warp][buf][lane] = h;
        __syncwarp();

        // ---- Recurrent matvec: acc starts from precomputed x-gates ----
        float2 acc[4];
#pragma unroll
        for (int g = 0; g < 4; g++) acc[g] = xg[g];

        const float4* hp4 = reinterpret_cast<const float4*>(sh[warp][buf]);
#pragma unroll
        for (int p = 0; p < 8; p++) {
            const float4 hv = hp4[p];
            const float2 ha = make_float2(hv.x, hv.y);
            const float2 hb = make_float2(hv.z, hv.w);
#pragma unroll
            for (int g = 0; g < 4; g++) {
                acc[g] = ffma2(wh[g][2 * p],     ha, acc[g]);
                acc[g] = ffma2(wh[g][2 * p + 1], hb, acc[g]);
            }
        }

        const float yi = acc[0].x + acc[0].y;
        const float yf = acc[1].x + acc[1].y;
        const float yg = acc[2].x + acc[2].y;
        const float yo = acc[3].x + acc[3].y;

        // MUFU issues (latency ~16, rt 8 shared) ...
        const float ti = tanh_hw(yi);
        const float tf = tanh_hw(yf);
        const float gc = tanh_hw(yg);
        const float to = tanh_hw(yo);

        // ... overlapped with INDEPENDENT work: x-gates for step t+1
        // (xc = x(t+1) arrived >1 step ago) + advance the load pipeline.
#pragma unroll
        for (int g = 0; g < 4; g++) {
            xg[g] = make_float2(bias[g], 0.0f);
#pragma unroll
            for (int q = 0; q < 5; q++) xg[g] = ffma2(wi[g][q], xc[q], xg[g]);
        }
#pragma unroll
        for (int q = 0; q < 5; q++) xc[q] = xn[q];
        {
            const int tn = (t + 3 < T) ? t + 3 : T - 1;
            const float2* nxt = xw + (size_t)tn * 5;
#pragma unroll
            for (int q = 0; q < 5; q++) xn[q] = nxt[q];
        }

        // consume tanh results
        const float ig = fmaf(0.5f, ti, 0.5f);
        const float fg = fmaf(0.5f, tf, 0.5f);
        const float og = fmaf(0.5f, to, 0.5f);

        c = fmaf(fg, c, ig * gc);
        h = og * tanh_hw(c);
    }

    // out[b] = sum_k h[k] * W_lin[0,k] + b_lin
    float v = h * wl;
#pragma unroll
    for (int off = 16; off; off >>= 1)
        v += __shfl_xor_sync(FULL_MASK, v, off);
    if (lane == 0) out[b] = v + b_lin[0];
}

extern "C" void kernel_launch(void* const* d_in, const int* in_sizes, int n_in,
                              void* d_out, int out_size)
{
    const float* x     = (const float*)d_in[0];
    const float* h0    = (const float*)d_in[1];
    const float* c0    = (const float*)d_in[2];
    const float* W_ih  = (const float*)d_in[3];
    const float* W_hh  = (const float*)d_in[4];
    const float* b_ih  = (const float*)d_in[5];
    const float* b_hh  = (const float*)d_in[6];
    const float* W_lin = (const float*)d_in[7];
    const float* b_lin = (const float*)d_in[8];
    float* out = (float*)d_out;

    // 4096 batches, 1 per warp, 4 warps per 128-thread block -> 1024 blocks
    lstm_r14<<<1024, 128>>>(x, h0, c0, W_ih, W_hh, b_ih, b_hh,
                            W_lin, b_lin, out);
}